// round 10
// baseline (speedup 1.0000x reference)
#include <cuda_runtime.h>
#include <cuda_bf16.h>
#include <math.h>
#include <stdint.h>

#define TOKENS 8192
#define DIM    4096
#define NEXP   256
#define TOPK   8

#define TM   64
#define TN   128                // experts per CTA (N-split)
#define BK   32                 // 2 x k16 per chunk
#define NCH  (DIM / BK)         // 128
#define NTH  256

#define ROWB   256              // 8 granules of 32B; granules 0..5 used
#define NROWS  (TM + TN)        // 192
#define STAGE  (NROWS * ROWB)   // 49152
#define SMEM_BYTES (2 * STAGE)  // 98304

// pre-split W: [c][n][6 granules x 32B]; granule j = sp*2+cq, words perm (P0,P4,P1,P5,P2,P6,P3,P7)
__device__ __align__(16) char g_ws[NCH * NEXP * 192];
// fp32 logits buffer
__device__ __align__(16) float g_lg[(size_t)TOKENS * NEXP];

__device__ __forceinline__ void mma_bf16(float* d,
                                         uint32_t a0, uint32_t a1, uint32_t a2, uint32_t a3,
                                         uint32_t b0, uint32_t b1) {
    asm volatile(
        "mma.sync.aligned.m16n8k16.row.col.f32.bf16.bf16.f32 "
        "{%0,%1,%2,%3},{%4,%5,%6,%7},{%8,%9},{%0,%1,%2,%3};"
        : "+f"(d[0]), "+f"(d[1]), "+f"(d[2]), "+f"(d[3])
        : "r"(a0), "r"(a1), "r"(a2), "r"(a3), "r"(b0), "r"(b1));
}

__device__ __forceinline__ uint32_t smem_u32(const void* p) {
    uint32_t a;
    asm("{ .reg .u64 t; cvta.to.shared.u64 t, %1; cvt.u32.u64 %0, t; }" : "=r"(a) : "l"(p));
    return a;
}
#define CP_ASYNC16(dst, src) \
    asm volatile("cp.async.cg.shared.global [%0], [%1], 16;" :: "r"(dst), "l"(src))
#define CP_COMMIT() asm volatile("cp.async.commit_group;" ::: "memory")
#define CP_WAIT0()  asm volatile("cp.async.wait_group 0;" ::: "memory")

// EXACT truncation 3-way split: v = h + m + l bit-exactly
__device__ __forceinline__ void tsplit3(float v, float* h, float* m, float* l) {
    float hh = __uint_as_float(__float_as_uint(v) & 0xFFFF0000u);
    float r  = v - hh;
    float mm = __uint_as_float(__float_as_uint(r) & 0xFFFF0000u);
    *h = hh; *m = mm; *l = r - mm;
}
__device__ __forceinline__ uint32_t packhi(float a, float b) {
    return __byte_perm(__float_as_uint(a), __float_as_uint(b), 0x7632);
}

// XLA logistic: 0.5 + 0.5 * tanh(0.5x)
__device__ __forceinline__ float xla_sigmoid(float v) {
    float x = 0.5f * v;
    float t;
    if (fabsf(x) < 0.0004f) {
        t = x;
    } else {
        float xc = fminf(fmaxf(x, -7.90531110763549805f), 7.90531110763549805f);
        float x2 = xc * xc;
        float p = -2.76076847742355e-16f;
        p = fmaf(p, x2, 2.00018790482477e-13f);
        p = fmaf(p, x2, -8.60467152213735e-11f);
        p = fmaf(p, x2, 5.12229709037114e-08f);
        p = fmaf(p, x2, 1.48572235717979e-05f);
        p = fmaf(p, x2, 6.37261928875436e-04f);
        p = fmaf(p, x2, 4.89352455891786e-03f);
        p = xc * p;
        float q = 1.19825839466702e-06f;
        q = fmaf(q, x2, 1.18534705686654e-04f);
        q = fmaf(q, x2, 2.26843463243900e-03f);
        q = fmaf(q, x2, 4.89352518554385e-03f);
        t = p / q;
    }
    return fmaf(0.5f, t, 0.5f);
}

// ============================================================================
// W prepass (unchanged numerics)
// ============================================================================
__global__ __launch_bounds__(256) void wsplit_kernel(const float* __restrict__ w) {
    int j = blockIdx.x * 256 + threadIdx.x;   // 32768 = n*128 + c
    int c = j & 127;
    int n = j >> 7;
    const float4* src = (const float4*)(w + (size_t)n * DIM + c * BK);
    float v[32];
    #pragma unroll
    for (int i = 0; i < 8; ++i) {
        float4 f = src[i];
        v[i*4+0] = f.x; v[i*4+1] = f.y; v[i*4+2] = f.z; v[i*4+3] = f.w;
    }
    float H[32], M[32], L[32];
    #pragma unroll
    for (int i = 0; i < 32; ++i) tsplit3(v[i], &H[i], &M[i], &L[i]);

    uint32_t* dst = (uint32_t*)(g_ws + ((size_t)c * NEXP + n) * 192);
    const int perm[8] = {0, 4, 1, 5, 2, 6, 3, 7};
    #pragma unroll
    for (int sp = 0; sp < 3; ++sp) {
        const float* S = (sp == 0) ? H : (sp == 1) ? M : L;
        #pragma unroll
        for (int cq = 0; cq < 2; ++cq) {
            #pragma unroll
            for (int wpos = 0; wpos < 8; ++wpos) {
                int pj = perm[wpos];
                int k0 = cq * 16 + 2 * pj;
                dst[(sp * 2 + cq) * 8 + wpos] = packhi(S[k0], S[k0 + 1]);
            }
        }
    }
}

// ============================================================================
// main GEMM kernel: 64 tokens x 128 experts per CTA, 2 CTAs/SM
// ============================================================================
__global__ __launch_bounds__(NTH, 2)
void gate_gemm_kernel(const float* __restrict__ x)
{
    extern __shared__ char smem[];
    const uint32_t sb = smem_u32(smem);
    const int tid    = threadIdx.x;
    const int lane   = tid & 31;
    const int wid    = tid >> 5;      // 8 warps
    const int warp_m = wid & 1;       // 2 x 32 tokens
    const int warp_n = wid >> 1;      // 4 x 32 experts
    const int t0     = blockIdx.x * TM;
    const int e0     = blockIdx.y * TN;
    const int fr     = lane >> 2;
    const int fc     = lane & 3;

    float am[2][4][4], ac[2][4][4];
    #pragma unroll
    for (int tm = 0; tm < 2; ++tm)
        #pragma unroll
        for (int tn = 0; tn < 4; ++tn)
            #pragma unroll
            for (int q = 0; q < 4; ++q) { am[tm][tn][q] = 0.f; ac[tm][tn][q] = 0.f; }

    // W staging: 128 rows x 12 units = 1536; thread does u = tid + 256*i, i=0..5
    uint32_t dstB[6], srcB[6];
    #pragma unroll
    for (int i = 0; i < 6; ++i) {
        int u  = tid + 256 * i;
        int n  = u / 12;
        int mi = u - n * 12;
        int r  = TM + n;
        dstB[i] = (uint32_t)(r * ROWB + (((mi >> 1) ^ (n & 3)) * 32) + (mi & 1) * 16);
        srcB[i] = (uint32_t)((e0 + n) * 192 + mi * 16);
    }

    // x staging: thread -> row xr = tid>>2, q2 = tid&3 (8 values at q2*8)
    const int xr  = tid >> 2;
    const int q2  = tid & 3;
    const int xcq = q2 >> 1;
    const int xj0 = (q2 & 1) * 4;    // pairs j0..j0+3
    const float* xsrc = x + (size_t)(t0 + xr) * DIM + q2 * 8;

    float4 ra0, ra1;

    auto issue = [&](int c, int s) {
        const uint32_t sbase = sb + (uint32_t)(s * STAGE);
        const char* wb = g_ws + (size_t)c * (NEXP * 192);
        #pragma unroll
        for (int i = 0; i < 6; ++i)
            CP_ASYNC16(sbase + dstB[i], (const void*)(wb + srcB[i]));
        CP_COMMIT();
        const float* p = xsrc + (size_t)c * BK;
        ra0 = *(const float4*)p;
        ra1 = *(const float4*)(p + 4);
    };

    auto finish_x = [&](int s) {
        float va[8] = {ra0.x, ra0.y, ra0.z, ra0.w, ra1.x, ra1.y, ra1.z, ra1.w};
        float H[8], M[8], L[8];
        #pragma unroll
        for (int i = 0; i < 8; ++i) tsplit3(va[i], &H[i], &M[i], &L[i]);
        uint32_t* base = (uint32_t*)(smem + s * STAGE + xr * ROWB);
        const int rx = xr & 3;
        #pragma unroll
        for (int sp = 0; sp < 3; ++sp) {
            const float* S = (sp == 0) ? H : (sp == 1) ? M : L;
            uint32_t* g = base + (((sp * 2 + xcq) ^ rx) * 8);
            #pragma unroll
            for (int p = 0; p < 4; ++p) {
                int j = xj0 + p;
                int wpos = (j & 3) * 2 + (j >> 2);
                g[wpos] = packhi(S[2 * p], S[2 * p + 1]);
            }
        }
    };

    // fragment row bases
    int arow[2][2];
    #pragma unroll
    for (int tm = 0; tm < 2; ++tm) {
        arow[tm][0] = warp_m * 32 + tm * 16 + fr;
        arow[tm][1] = arow[tm][0] + 8;
    }
    int brow[4];
    #pragma unroll
    for (int tn = 0; tn < 4; ++tn) brow[tn] = TM + warp_n * 32 + tn * 8 + fr;

    // prologue
    issue(0, 0);
    finish_x(0);
    CP_WAIT0();
    __syncthreads();

    for (int c = 0; c < NCH; ++c) {
        const int s = c & 1;
        if (c + 1 < NCH) issue(c + 1, s ^ 1);

        const char* st = smem + s * STAGE;
        #pragma unroll
        for (int cq = 0; cq < 2; ++cq) {
            uint2 A[3][2][2];   // [sp][tm][hf]
            #pragma unroll
            for (int tm = 0; tm < 2; ++tm)
                #pragma unroll
                for (int hf = 0; hf < 2; ++hf) {
                    int r = arow[tm][hf];
                    const char* pr = st + r * ROWB;
                    const int rx = r & 3;
                    A[0][tm][hf] = *(const uint2*)(pr + (((0 * 2 + cq) ^ rx) * 32) + fc * 8);
                    A[1][tm][hf] = *(const uint2*)(pr + (((1 * 2 + cq) ^ rx) * 32) + fc * 8);
                    A[2][tm][hf] = *(const uint2*)(pr + (((2 * 2 + cq) ^ rx) * 32) + fc * 8);
                }
            #pragma unroll
            for (int tn = 0; tn < 4; ++tn) {
                int r = brow[tn];
                const char* pr = st + r * ROWB;
                const int rx = r & 3;
                uint2 bh = *(const uint2*)(pr + (((0 * 2 + cq) ^ rx) * 32) + fc * 8);
                uint2 bm = *(const uint2*)(pr + (((1 * 2 + cq) ^ rx) * 32) + fc * 8);
                uint2 bl = *(const uint2*)(pr + (((2 * 2 + cq) ^ rx) * 32) + fc * 8);
                #pragma unroll
                for (int tm = 0; tm < 2; ++tm) {
                    float* dm = am[tm][tn];
                    float* dc = ac[tm][tn];
                    uint2 ah0 = A[0][tm][0], ah1 = A[0][tm][1];
                    uint2 am0 = A[1][tm][0], am1 = A[1][tm][1];
                    uint2 al0 = A[2][tm][0], al1 = A[2][tm][1];
                    mma_bf16(dm, ah0.x, ah1.x, ah0.y, ah1.y, bh.x, bh.y);  // hh
                    mma_bf16(dc, ah0.x, ah1.x, ah0.y, ah1.y, bm.x, bm.y);  // hm
                    mma_bf16(dc, am0.x, am1.x, am0.y, am1.y, bh.x, bh.y);  // mh
                    mma_bf16(dc, am0.x, am1.x, am0.y, am1.y, bm.x, bm.y);  // mm
                    mma_bf16(dc, ah0.x, ah1.x, ah0.y, ah1.y, bl.x, bl.y);  // hl
                    mma_bf16(dc, al0.x, al1.x, al0.y, al1.y, bh.x, bh.y);  // lh
                }
            }
        }

        if (c + 1 < NCH) finish_x(s ^ 1);
        CP_WAIT0();
        __syncthreads();
    }

    // epilogue: logits -> gmem buffer
    #pragma unroll
    for (int tm = 0; tm < 2; ++tm) {
        int r = warp_m * 32 + tm * 16 + fr;
        #pragma unroll
        for (int tn = 0; tn < 4; ++tn) {
            int cc = e0 + warp_n * 32 + tn * 8 + fc * 2;
            float v0 = am[tm][tn][0] + ac[tm][tn][0];
            float v1 = am[tm][tn][1] + ac[tm][tn][1];
            float v2 = am[tm][tn][2] + ac[tm][tn][2];
            float v3 = am[tm][tn][3] + ac[tm][tn][3];
            *(float2*)(g_lg + (size_t)(t0 + r) * NEXP + cc)     = make_float2(v0, v1);
            *(float2*)(g_lg + (size_t)(t0 + r + 8) * NEXP + cc) = make_float2(v2, v3);
        }
    }
}

// ============================================================================
// top-8 kernel: warp per token
// ============================================================================
__global__ __launch_bounds__(128) void top8_kernel(float* __restrict__ out, int write_idx) {
    const int lane = threadIdx.x & 31;
    const int t    = blockIdx.x * 4 + (threadIdx.x >> 5);

    float v[8];
    #pragma unroll
    for (int j = 0; j < 8; ++j)
        v[j] = xla_sigmoid(g_lg[(size_t)t * NEXP + lane + j * 32]);

    float topv[8];
    int   topi[8];
    unsigned used = 0;

    #pragma unroll
    for (int r = 0; r < 8; ++r) {
        float best = -INFINITY;
        int   bidx = 0x7fffffff;
        #pragma unroll
        for (int j = 0; j < 8; ++j) {
            if (!((used >> j) & 1u)) {
                float val = v[j];
                int   id  = lane + j * 32;
                if (val > best || (val == best && id < bidx)) { best = val; bidx = id; }
            }
        }
        #pragma unroll
        for (int off = 16; off > 0; off >>= 1) {
            float ov = __shfl_xor_sync(0xffffffffu, best, off);
            int   oi = __shfl_xor_sync(0xffffffffu, bidx, off);
            if (ov > best || (ov == best && oi < bidx)) { best = ov; bidx = oi; }
        }
        topv[r] = best;
        topi[r] = bidx;
        if ((bidx & 31) == lane) used |= 1u << (bidx >> 5);
    }

    float sum = 0.f;
    #pragma unroll
    for (int r = 0; r < 8; ++r) sum += topv[r];
    float inv = 1.f / sum;

    if (lane == 0) {
        #pragma unroll
        for (int r = 0; r < 8; ++r)
            out[(size_t)t * TOPK + r] = topv[r] * inv;
        if (write_idx) {
            #pragma unroll
            for (int r = 0; r < 8; ++r)
                out[(size_t)TOKENS * TOPK + (size_t)t * TOPK + r] = (float)topi[r];
        }
    }
}

extern "C" void kernel_launch(void* const* d_in, const int* in_sizes, int n_in,
                              void* d_out, int out_size)
{
    const float* x = (const float*)d_in[0];   // [TOKENS, DIM]
    const float* w = (const float*)d_in[1];   // [NEXP, DIM]
    float* out = (float*)d_out;

    int write_idx = (out_size >= 2 * TOKENS * TOPK) ? 1 : 0;

    cudaFuncSetAttribute(gate_gemm_kernel, cudaFuncAttributeMaxDynamicSharedMemorySize, SMEM_BYTES);

    wsplit_kernel<<<(NEXP * NCH) / 256, 256>>>(w);
    dim3 grid(TOKENS / TM, NEXP / TN);
    gate_gemm_kernel<<<grid, NTH, SMEM_BYTES>>>(x);
    top8_kernel<<<TOKENS / 4, 128>>>(out, write_idx);
}